// round 1
// baseline (speedup 1.0000x reference)
#include <cuda_runtime.h>

#define BN_TOT 16384   // B*N = 4*4096
#define NPTS   4096
#define KK     40

// ---------------- scratch (device globals; no allocation allowed) -------------
__device__ int      d_idx[BN_TOT * KK];
__device__ float    d_feats[BN_TOT * 192];   // [x1 | x2 | x3]
__device__ float    d_cst[BN_TOT * 64];      // reused: cst for stage2, then stage3
__device__ float    d_h7[BN_TOT * 512];
__device__ float    d_h8[BN_TOT * 256];
__device__ unsigned d_gmax[4 * 1024];        // per-batch conv6 max (order-preserving uint)
__device__ float    d_wd3[64 * 64];          // W3[:,64:128]-W3[:,0:64]
__device__ float    d_wd5[64 * 64];
__device__ float    d_gterm[4 * 512];        // g @ W7[:, :1024]^T  per batch

__device__ __forceinline__ unsigned fkey(float f) {
    unsigned u = __float_as_uint(f);
    return (u & 0x80000000u) ? ~u : (u | 0x80000000u);
}
__device__ __forceinline__ float fdecode(unsigned k) {
    return (k & 0x80000000u) ? __uint_as_float(k ^ 0x80000000u) : __uint_as_float(~k);
}
__device__ __forceinline__ float lrelu(float v) { return v >= 0.f ? v : 0.2f * v; }

// ---------------- prep: weight diffs + zero gmax ------------------------------
__global__ void prep_kernel(const float* __restrict__ W3, const float* __restrict__ W5) {
    int t = blockIdx.x * blockDim.x + threadIdx.x;
    if (t < 4096) {
        int c = t >> 6, i = t & 63;
        d_wd3[t] = W3[c * 128 + 64 + i] - W3[c * 128 + i];
    } else if (t < 8192) {
        int u = t - 4096; int c = u >> 6, i = u & 63;
        d_wd5[u] = W5[c * 128 + 64 + i] - W5[c * 128 + i];
    } else if (t < 12288) {
        d_gmax[t - 8192] = 0u;
    }
}

// ---------------- KNN: radix top-40 per query ---------------------------------
__global__ void __launch_bounds__(128) knn_kernel(const float* __restrict__ x) {
    const int q = blockIdx.x;
    const int b = q >> 12, n = q & 4095;
    const int tid = threadIdx.x;
    __shared__ unsigned key[NPTS];
    __shared__ unsigned hist[256];
    __shared__ unsigned sc[2];
    __shared__ int cHi, cEq;

    const float* xb = x + b * 3 * NPTS;
    float cx = xb[n], cy = xb[NPTS + n], cz = xb[2 * NPTS + n];
    float xxi = cx * cx + cy * cy + cz * cz;

    for (int j = tid; j < NPTS; j += 128) {
        float px = xb[j], py = xb[NPTS + j], pz = xb[2 * NPTS + j];
        float dot = cx * px + cy * py + cz * pz;
        float xxj = px * px + py * py + pz * pz;
        float d = (2.f * dot - xxi) - xxj;   // = -||xi-xj||^2, larger = nearer
        key[j] = fkey(d);
    }

    unsigned prefix = 0, need = KK;
    for (int pass = 0; pass < 4; ++pass) {
        int shift = 24 - 8 * pass;
        unsigned himask = (pass == 0) ? 0u : (0xFFFFFFFFu << (shift + 8));
        for (int i2 = tid; i2 < 256; i2 += 128) hist[i2] = 0u;
        __syncthreads();
        for (int j = tid; j < NPTS; j += 128) {
            unsigned k = key[j];
            if ((k & himask) == (prefix & himask))
                atomicAdd(&hist[(k >> shift) & 255], 1u);
        }
        __syncthreads();
        if (tid < 32) {
            unsigned part[8]; unsigned s = 0;
            #pragma unroll
            for (int r = 0; r < 8; r++) { part[r] = hist[255 - tid * 8 - r]; s += part[r]; }
            unsigned inc = s;
            #pragma unroll
            for (int o = 1; o < 32; o <<= 1) {
                unsigned v = __shfl_up_sync(0xffffffffu, inc, o);
                if (tid >= o) inc += v;
            }
            unsigned excl = inc - s;
            unsigned ball = __ballot_sync(0xffffffffu, (excl < need) && (need <= inc));
            int lane = __ffs(ball) - 1;
            if (tid == lane) {
                unsigned rem = need - excl, cacc = 0; int r = 0;
                for (; r < 8; r++) { if (cacc + part[r] >= rem) break; cacc += part[r]; }
                unsigned v = 255u - (unsigned)(tid * 8) - (unsigned)r;
                sc[0] = prefix | (v << shift);
                sc[1] = rem - cacc;
            }
        }
        __syncthreads();
        prefix = sc[0]; need = sc[1];
        __syncthreads();
    }

    if (tid == 0) { cHi = 0; cEq = 0; }
    __syncthreads();
    int base = q * KK;
    int takeEq = (int)need;
    int nAbove = KK - takeEq;
    for (int j = tid; j < NPTS; j += 128) {
        unsigned k = key[j];
        if (k > prefix) {
            int p = atomicAdd(&cHi, 1);
            d_idx[base + p] = j;
        } else if (k == prefix) {
            int p = atomicAdd(&cEq, 1);
            if (p < takeEq) d_idx[base + nAbove + p] = j;
        }
    }
}

// ---------------- stage 1: edge(xyz) -> conv1 -> conv2 -> max -> x1 -----------
__global__ void __launch_bounds__(64) stage1_kernel(
    const float* __restrict__ x,
    const float* __restrict__ W1, const float* __restrict__ s1, const float* __restrict__ b1,
    const float* __restrict__ W2, const float* __restrict__ s2, const float* __restrict__ b2) {
    int q = blockIdx.x; int b = q >> 12; int n = q & 4095;
    int c = threadIdx.x;
    __shared__ __align__(16) float nb[KK][4];
    __shared__ __align__(16) float h1[KK][64];
    __shared__ int sj[KK];
    const float* xb = x + b * 3 * NPTS;
    if (c < KK) sj[c] = d_idx[q * KK + c];
    __syncthreads();
    if (c < KK) {
        int j = sj[c];
        nb[c][0] = xb[j]; nb[c][1] = xb[NPTS + j]; nb[c][2] = xb[2 * NPTS + j];
    }
    float cx = xb[n], cy = xb[NPTS + n], cz = xb[2 * NPTS + n];
    float w0 = W1[c * 6 + 0], w1 = W1[c * 6 + 1], w2 = W1[c * 6 + 2];
    float cst = (W1[c * 6 + 3] - w0) * cx + (W1[c * 6 + 4] - w1) * cy + (W1[c * 6 + 5] - w2) * cz;
    float sc1 = s1[c], sb1 = b1[c];
    __syncthreads();
    #pragma unroll 8
    for (int k = 0; k < KK; k++) {
        float a = cst + w0 * nb[k][0] + w1 * nb[k][1] + w2 * nb[k][2];
        h1[k][c] = lrelu(a * sc1 + sb1);
    }
    __syncthreads();
    float w[64];
    #pragma unroll
    for (int i = 0; i < 16; i++) ((float4*)w)[i] = ((const float4*)(W2 + c * 64))[i];
    float sc2 = s2[c], sb2 = b2[c];
    float m = -3.4e38f;
    #pragma unroll 2
    for (int k = 0; k < KK; k++) {
        float a0 = 0, a1 = 0, a2 = 0, a3 = 0;
        #pragma unroll
        for (int i = 0; i < 64; i += 4) {
            float4 h4 = *(const float4*)&h1[k][i];
            a0 += w[i] * h4.x; a1 += w[i + 1] * h4.y; a2 += w[i + 2] * h4.z; a3 += w[i + 3] * h4.w;
        }
        m = fmaxf(m, lrelu(((a0 + a1) + (a2 + a3)) * sc2 + sb2));
    }
    d_feats[q * 192 + c] = m;
}

// ---------------- stage 2: edge(x1) -> conv3 -> conv4 -> max -> x2 ------------
__global__ void __launch_bounds__(64) stage2_kernel(
    const float* __restrict__ W3, const float* __restrict__ s3, const float* __restrict__ b3,
    const float* __restrict__ W4, const float* __restrict__ s4, const float* __restrict__ b4) {
    int q = blockIdx.x; int c = threadIdx.x;
    __shared__ __align__(16) float nbF[KK][64];
    __shared__ __align__(16) float h[KK][64];
    __shared__ int sj[KK];
    if (c < KK) sj[c] = d_idx[q * KK + c];
    __syncthreads();
    int rowbase = q & ~4095;
    #pragma unroll 8
    for (int k = 0; k < KK; k++) nbF[k][c] = d_feats[(rowbase + sj[k]) * 192 + c];
    float w[64];
    #pragma unroll
    for (int i = 0; i < 16; i++) ((float4*)w)[i] = ((const float4*)(W3 + c * 128))[i];
    float cc = d_cst[q * 64 + c];
    float sc = s3[c], sb = b3[c];
    __syncthreads();
    #pragma unroll 2
    for (int k = 0; k < KK; k++) {
        float a0 = 0, a1 = 0, a2 = 0, a3 = 0;
        #pragma unroll
        for (int i = 0; i < 64; i += 4) {
            float4 h4 = *(const float4*)&nbF[k][i];
            a0 += w[i] * h4.x; a1 += w[i + 1] * h4.y; a2 += w[i + 2] * h4.z; a3 += w[i + 3] * h4.w;
        }
        h[k][c] = lrelu((cc + (a0 + a1) + (a2 + a3)) * sc + sb);
    }
    __syncthreads();
    #pragma unroll
    for (int i = 0; i < 16; i++) ((float4*)w)[i] = ((const float4*)(W4 + c * 64))[i];
    float sc4 = s4[c], sb4 = b4[c];
    float m = -3.4e38f;
    #pragma unroll 2
    for (int k = 0; k < KK; k++) {
        float a0 = 0, a1 = 0, a2 = 0, a3 = 0;
        #pragma unroll
        for (int i = 0; i < 64; i += 4) {
            float4 h4 = *(const float4*)&h[k][i];
            a0 += w[i] * h4.x; a1 += w[i + 1] * h4.y; a2 += w[i + 2] * h4.z; a3 += w[i + 3] * h4.w;
        }
        m = fmaxf(m, lrelu(((a0 + a1) + (a2 + a3)) * sc4 + sb4));
    }
    d_feats[q * 192 + 64 + c] = m;
}

// ---------------- stage 3: edge(x2) -> conv5 -> max -> x3 ---------------------
__global__ void __launch_bounds__(64) stage3_kernel(
    const float* __restrict__ W5, const float* __restrict__ s5, const float* __restrict__ b5) {
    int q = blockIdx.x; int c = threadIdx.x;
    __shared__ __align__(16) float nbF[KK][64];
    __shared__ int sj[KK];
    if (c < KK) sj[c] = d_idx[q * KK + c];
    __syncthreads();
    int rowbase = q & ~4095;
    #pragma unroll 8
    for (int k = 0; k < KK; k++) nbF[k][c] = d_feats[(rowbase + sj[k]) * 192 + 64 + c];
    float w[64];
    #pragma unroll
    for (int i = 0; i < 16; i++) ((float4*)w)[i] = ((const float4*)(W5 + c * 128))[i];
    float cc = d_cst[q * 64 + c];
    float sc = s5[c], sb = b5[c];
    __syncthreads();
    float m = -3.4e38f;
    #pragma unroll 2
    for (int k = 0; k < KK; k++) {
        float a0 = 0, a1 = 0, a2 = 0, a3 = 0;
        #pragma unroll
        for (int i = 0; i < 64; i += 4) {
            float4 h4 = *(const float4*)&nbF[k][i];
            a0 += w[i] * h4.x; a1 += w[i + 1] * h4.y; a2 += w[i + 2] * h4.z; a3 += w[i + 3] * h4.w;
        }
        m = fmaxf(m, lrelu((cc + (a0 + a1) + (a2 + a3)) * sc + sb));
    }
    d_feats[q * 192 + 128 + c] = m;
}

// ---------------- generic tiled GEMM: C[M,N] = A[M,K] @ B[N,K]^T --------------
// EPI: 0 plain store, 1 scale/bias/lrelu, 2 +gterm then scale/bias/lrelu,
//      3 conv6 (col-max + atomicMax, no store), 4 conv9 (bias, transposed store)
template <int EPI>
__global__ void __launch_bounds__(256) gemm_k(
    const float* __restrict__ A, int lda,
    const float* __restrict__ B, int ldb, int nrows,
    int K, float* __restrict__ C, int ldc,
    const float* __restrict__ sv, const float* __restrict__ bv) {
    __shared__ __align__(16) float As[16][68];
    __shared__ __align__(16) float Bs[16][68];
    int tid = threadIdx.x;
    int tx = tid & 15, ty = tid >> 4;
    int mBase = blockIdx.y * 64, nBase = blockIdx.x * 64;
    int lr = tid >> 2, lc = (tid & 3) * 4;
    const float* Ap = A + (mBase + lr) * lda + lc;
    const float* Bp = B + (nBase + lr) * ldb + lc;
    bool bval = (nBase + lr) < nrows;
    float acc[4][4] = {};
    for (int kt = 0; kt < K; kt += 16) {
        float4 av = *(const float4*)(Ap + kt);
        float4 bw = bval ? *(const float4*)(Bp + kt) : make_float4(0.f, 0.f, 0.f, 0.f);
        __syncthreads();
        As[lc + 0][lr] = av.x; As[lc + 1][lr] = av.y; As[lc + 2][lr] = av.z; As[lc + 3][lr] = av.w;
        Bs[lc + 0][lr] = bw.x; Bs[lc + 1][lr] = bw.y; Bs[lc + 2][lr] = bw.z; Bs[lc + 3][lr] = bw.w;
        __syncthreads();
        #pragma unroll
        for (int kk = 0; kk < 16; kk++) {
            float4 a4 = *(const float4*)&As[kk][ty * 4];
            float4 b4 = *(const float4*)&Bs[kk][tx * 4];
            acc[0][0] += a4.x * b4.x; acc[0][1] += a4.x * b4.y; acc[0][2] += a4.x * b4.z; acc[0][3] += a4.x * b4.w;
            acc[1][0] += a4.y * b4.x; acc[1][1] += a4.y * b4.y; acc[1][2] += a4.y * b4.z; acc[1][3] += a4.y * b4.w;
            acc[2][0] += a4.z * b4.x; acc[2][1] += a4.z * b4.y; acc[2][2] += a4.z * b4.z; acc[2][3] += a4.z * b4.w;
            acc[3][0] += a4.w * b4.x; acc[3][1] += a4.w * b4.y; acc[3][2] += a4.w * b4.z; acc[3][3] += a4.w * b4.w;
        }
    }

    if (EPI == 3) {
        int bb = mBase >> 12;
        float cm[4];
        #pragma unroll
        for (int ni = 0; ni < 4; ni++) {
            int nn = nBase + tx * 4 + ni;
            float s = sv[nn], bbv = bv[nn];
            float m = lrelu(acc[0][ni] * s + bbv);
            m = fmaxf(m, lrelu(acc[1][ni] * s + bbv));
            m = fmaxf(m, lrelu(acc[2][ni] * s + bbv));
            m = fmaxf(m, lrelu(acc[3][ni] * s + bbv));
            cm[ni] = m;
        }
        __syncthreads();
        #pragma unroll
        for (int ni = 0; ni < 4; ni++) As[ty][tx * 4 + ni] = cm[ni];
        __syncthreads();
        if (tid < 64) {
            float m = As[0][tid];
            #pragma unroll
            for (int r = 1; r < 16; r++) m = fmaxf(m, As[r][tid]);
            atomicMax(&d_gmax[bb * 1024 + nBase + tid], fkey(m));
        }
        return;
    }

    #pragma unroll
    for (int mi = 0; mi < 4; mi++) {
        int m = mBase + ty * 4 + mi;
        #pragma unroll
        for (int ni = 0; ni < 4; ni++) {
            int n = nBase + tx * 4 + ni;
            float a = acc[mi][ni];
            if (EPI == 0) {
                C[m * ldc + n] = a;
            } else if (EPI == 1) {
                C[m * ldc + n] = lrelu(a * sv[n] + bv[n]);
            } else if (EPI == 2) {
                int bb = m >> 12;
                C[m * ldc + n] = lrelu((a + d_gterm[bb * 512 + n]) * sv[n] + bv[n]);
            } else { // EPI == 4 : conv9, transposed output (B,63,N)
                if (n < 63) {
                    int bb = m >> 12; int nn = m & 4095;
                    C[(bb * 63 + n) * 4096 + nn] = a + bv[n];
                }
            }
        }
    }
}

// ---------------- gterm: g[b] @ W7[:, :1024]^T --------------------------------
__global__ void __launch_bounds__(256) gterm_kernel(const float* __restrict__ W7) {
    int b = blockIdx.x >> 3;
    int cg = blockIdx.x & 7;   // group of 64 couts
    __shared__ float gs[1024];
    __shared__ float warpsum[8];
    int tid = threadIdx.x;
    for (int i = tid; i < 1024; i += 256) gs[i] = fdecode(d_gmax[b * 1024 + i]);
    __syncthreads();
    for (int cl = 0; cl < 64; cl++) {
        int cOut = cg * 64 + cl;
        float4 wv = ((const float4*)(W7 + cOut * 1216))[tid];
        float4 g4 = *(const float4*)&gs[tid * 4];
        float p = wv.x * g4.x + wv.y * g4.y + wv.z * g4.z + wv.w * g4.w;
        #pragma unroll
        for (int o = 16; o > 0; o >>= 1) p += __shfl_down_sync(0xffffffffu, p, o);
        if ((tid & 31) == 0) warpsum[tid >> 5] = p;
        __syncthreads();
        if (tid == 0) {
            float s = 0;
            #pragma unroll
            for (int r = 0; r < 8; r++) s += warpsum[r];
            d_gterm[b * 512 + cOut] = s;
        }
        __syncthreads();
    }
}

// ---------------- host --------------------------------------------------------
extern "C" void kernel_launch(void* const* d_in, const int* in_sizes, int n_in,
                              void* d_out, int out_size) {
    const float* x  = (const float*)d_in[0];
    const float* W1 = (const float*)d_in[1];
    const float* s1 = (const float*)d_in[2];
    const float* b1 = (const float*)d_in[3];
    const float* W2 = (const float*)d_in[4];
    const float* s2 = (const float*)d_in[5];
    const float* b2 = (const float*)d_in[6];
    const float* W3 = (const float*)d_in[7];
    const float* s3 = (const float*)d_in[8];
    const float* b3 = (const float*)d_in[9];
    const float* W4 = (const float*)d_in[10];
    const float* s4 = (const float*)d_in[11];
    const float* b4 = (const float*)d_in[12];
    const float* W5 = (const float*)d_in[13];
    const float* s5 = (const float*)d_in[14];
    const float* b5 = (const float*)d_in[15];
    const float* W6 = (const float*)d_in[16];
    const float* s6 = (const float*)d_in[17];
    const float* b6 = (const float*)d_in[18];
    const float* W7 = (const float*)d_in[19];
    const float* s7 = (const float*)d_in[20];
    const float* b7 = (const float*)d_in[21];
    const float* W8 = (const float*)d_in[22];
    const float* s8 = (const float*)d_in[23];
    const float* b8 = (const float*)d_in[24];
    const float* W9 = (const float*)d_in[25];
    const float* b9 = (const float*)d_in[26];
    float* out = (float*)d_out;

    float *feats, *cst, *h7, *h8, *wd3, *wd5;
    cudaGetSymbolAddress((void**)&feats, d_feats);
    cudaGetSymbolAddress((void**)&cst,   d_cst);
    cudaGetSymbolAddress((void**)&h7,    d_h7);
    cudaGetSymbolAddress((void**)&h8,    d_h8);
    cudaGetSymbolAddress((void**)&wd3,   d_wd3);
    cudaGetSymbolAddress((void**)&wd5,   d_wd5);

    prep_kernel<<<48, 256>>>(W3, W5);
    knn_kernel<<<BN_TOT, 128>>>(x);
    stage1_kernel<<<BN_TOT, 64>>>(x, W1, s1, b1, W2, s2, b2);
    // cst for stage2: x1 @ (W3hi - W3lo)^T
    gemm_k<0><<<dim3(1, 256), 256>>>(feats, 192, wd3, 64, 64, 64, cst, 64, nullptr, nullptr);
    stage2_kernel<<<BN_TOT, 64>>>(W3, s3, b3, W4, s4, b4);
    // cst for stage3: x2 @ (W5hi - W5lo)^T
    gemm_k<0><<<dim3(1, 256), 256>>>(feats + 64, 192, wd5, 64, 64, 64, cst, 64, nullptr, nullptr);
    stage3_kernel<<<BN_TOT, 64>>>(W5, s5, b5);
    // conv6 + global max over N (per batch, per channel)
    gemm_k<3><<<dim3(16, 256), 256>>>(feats, 192, W6, 192, 1024, 192, nullptr, 0, s6, b6);
    // gterm[b] = g[b] @ W7[:, :1024]^T
    gterm_kernel<<<32, 256>>>(W7);
    // conv7 on feature part only (K=192) + gterm in epilogue
    gemm_k<2><<<dim3(8, 256), 256>>>(feats, 192, W7 + 1024, 1216, 512, 192, h7, 512, s7, b7);
    // conv8
    gemm_k<1><<<dim3(4, 256), 256>>>(h7, 512, W8, 512, 256, 512, h8, 256, s8, b8);
    // conv9 -> transposed output (B, 63, N)
    gemm_k<4><<<dim3(1, 256), 256>>>(h8, 256, W9, 256, 63, 256, out, 0, nullptr, b9);
}

// round 3
// speedup vs baseline: 1.0158x; 1.0158x over previous
#include <cuda_runtime.h>

#define BN_TOT 16384   // B*N = 4*4096
#define NPTS   4096
#define KK     40

typedef unsigned long long ull;

// ---------------- scratch (device globals; no allocation allowed) -------------
__device__ int      d_idx[BN_TOT * KK];
__device__ float    d_feats[BN_TOT * 192];   // [x1 | x2 | x3]
__device__ float    d_cst[BN_TOT * 64];      // reused: cst for stage2, then stage3
__device__ float    d_h7[BN_TOT * 512];
__device__ float    d_h8[BN_TOT * 256];
__device__ unsigned d_gmax[4 * 1024];        // per-batch conv6 max (order-preserving uint)
__device__ float    d_wd3[64 * 64];          // W3[:,64:128]-W3[:,0:64]
__device__ float    d_wd5[64 * 64];
__device__ float    d_gterm[4 * 512];        // g @ W7[:, :1024]^T  per batch

__device__ __forceinline__ unsigned fkey(float f) {
    unsigned u = __float_as_uint(f);
    return (u & 0x80000000u) ? ~u : (u | 0x80000000u);
}
__device__ __forceinline__ float fdecode(unsigned k) {
    return (k & 0x80000000u) ? __uint_as_float(k ^ 0x80000000u) : __uint_as_float(~k);
}
__device__ __forceinline__ float lrelu(float v) { return v >= 0.f ? v : 0.2f * v; }

// packed fp32x2 FMA (Blackwell): d.lo=a.lo*b.lo+c.lo, d.hi=a.hi*b.hi+c.hi
__device__ __forceinline__ ull fma2(ull a, ull b, ull c) {
    ull d;
    asm("fma.rn.f32x2 %0, %1, %2, %3;" : "=l"(d) : "l"(a), "l"(b), "l"(c));
    return d;
}
__device__ __forceinline__ float red2(ull a) {
    float x, y;
    asm("mov.b64 {%0, %1}, %2;" : "=f"(x), "=f"(y) : "l"(a));
    return x + y;
}

// ---------------- prep: weight diffs + zero gmax ------------------------------
__global__ void prep_kernel(const float* __restrict__ W3, const float* __restrict__ W5) {
    int t = blockIdx.x * blockDim.x + threadIdx.x;
    if (t < 4096) {
        int c = t >> 6, i = t & 63;
        d_wd3[t] = W3[c * 128 + 64 + i] - W3[c * 128 + i];
    } else if (t < 8192) {
        int u = t - 4096; int c = u >> 6, i = u & 63;
        d_wd5[u] = W5[c * 128 + 64 + i] - W5[c * 128 + i];
    } else if (t < 12288) {
        d_gmax[t - 8192] = 0u;
    }
}

// ---------------- KNN: radix top-40 per query ---------------------------------
__global__ void __launch_bounds__(128) knn_kernel(const float* __restrict__ x) {
    const int q = blockIdx.x;
    const int b = q >> 12, n = q & 4095;
    const int tid = threadIdx.x;
    __shared__ unsigned key[NPTS];
    __shared__ unsigned hist[256];
    __shared__ unsigned sc[2];
    __shared__ int cHi, cEq;

    const float* xb = x + b * 3 * NPTS;
    float cx = xb[n], cy = xb[NPTS + n], cz = xb[2 * NPTS + n];
    float xxi = cx * cx + cy * cy + cz * cz;

    for (int j = tid; j < NPTS; j += 128) {
        float px = xb[j], py = xb[NPTS + j], pz = xb[2 * NPTS + j];
        float dot = cx * px + cy * py + cz * pz;
        float xxj = px * px + py * py + pz * pz;
        float d = (2.f * dot - xxi) - xxj;   // = -||xi-xj||^2, larger = nearer
        key[j] = fkey(d);
    }

    unsigned prefix = 0, need = KK;
    for (int pass = 0; pass < 4; ++pass) {
        int shift = 24 - 8 * pass;
        unsigned himask = (pass == 0) ? 0u : (0xFFFFFFFFu << (shift + 8));
        for (int i2 = tid; i2 < 256; i2 += 128) hist[i2] = 0u;
        __syncthreads();
        for (int j = tid; j < NPTS; j += 128) {
            unsigned k = key[j];
            if ((k & himask) == (prefix & himask))
                atomicAdd(&hist[(k >> shift) & 255], 1u);
        }
        __syncthreads();
        if (tid < 32) {
            unsigned part[8]; unsigned s = 0;
            #pragma unroll
            for (int r = 0; r < 8; r++) { part[r] = hist[255 - tid * 8 - r]; s += part[r]; }
            unsigned inc = s;
            #pragma unroll
            for (int o = 1; o < 32; o <<= 1) {
                unsigned v = __shfl_up_sync(0xffffffffu, inc, o);
                if (tid >= o) inc += v;
            }
            unsigned excl = inc - s;
            unsigned ball = __ballot_sync(0xffffffffu, (excl < need) && (need <= inc));
            int lane = __ffs(ball) - 1;
            if (tid == lane) {
                unsigned rem = need - excl, cacc = 0; int r = 0;
                for (; r < 8; r++) { if (cacc + part[r] >= rem) break; cacc += part[r]; }
                unsigned v = 255u - (unsigned)(tid * 8) - (unsigned)r;
                sc[0] = prefix | (v << shift);
                sc[1] = rem - cacc;
            }
        }
        __syncthreads();
        prefix = sc[0]; need = sc[1];
        __syncthreads();
    }

    if (tid == 0) { cHi = 0; cEq = 0; }
    __syncthreads();
    int base = q * KK;
    int takeEq = (int)need;
    int nAbove = KK - takeEq;
    for (int j = tid; j < NPTS; j += 128) {
        unsigned k = key[j];
        if (k > prefix) {
            int p = atomicAdd(&cHi, 1);
            d_idx[base + p] = j;
        } else if (k == prefix) {
            int p = atomicAdd(&cEq, 1);
            if (p < takeEq) d_idx[base + nAbove + p] = j;
        }
    }
}

// ---------------- stage 1: edge(xyz) -> conv1 -> conv2 -> max -> x1 -----------
__global__ void __launch_bounds__(64) stage1_kernel(
    const float* __restrict__ x,
    const float* __restrict__ W1, const float* __restrict__ s1, const float* __restrict__ b1,
    const float* __restrict__ W2, const float* __restrict__ s2, const float* __restrict__ b2) {
    int q = blockIdx.x; int b = q >> 12; int n = q & 4095;
    int c = threadIdx.x;
    __shared__ __align__(16) float nb[KK][4];
    __shared__ __align__(16) float h1[KK][64];
    __shared__ int sj[KK];
    const float* xb = x + b * 3 * NPTS;
    if (c < KK) sj[c] = d_idx[q * KK + c];
    __syncthreads();
    if (c < KK) {
        int j = sj[c];
        nb[c][0] = xb[j]; nb[c][1] = xb[NPTS + j]; nb[c][2] = xb[2 * NPTS + j];
    }
    float cx = xb[n], cy = xb[NPTS + n], cz = xb[2 * NPTS + n];
    float w0 = W1[c * 6 + 0], w1 = W1[c * 6 + 1], w2 = W1[c * 6 + 2];
    float cst = (W1[c * 6 + 3] - w0) * cx + (W1[c * 6 + 4] - w1) * cy + (W1[c * 6 + 5] - w2) * cz;
    float sc1 = s1[c], sb1 = b1[c];
    __syncthreads();
    #pragma unroll 8
    for (int k = 0; k < KK; k++) {
        float a = cst + w0 * nb[k][0] + w1 * nb[k][1] + w2 * nb[k][2];
        h1[k][c] = lrelu(a * sc1 + sb1);
    }
    __syncthreads();
    ulonglong2 w2r[16];
    #pragma unroll
    for (int i = 0; i < 16; i++) w2r[i] = ((const ulonglong2*)(W2 + c * 64))[i];
    float sc2 = s2[c], sb2 = b2[c];
    float m = -3.4e38f;
    #pragma unroll 2
    for (int k = 0; k < KK; k++) {
        ull a0 = 0ULL, a1 = 0ULL;
        const ulonglong2* hp = (const ulonglong2*)&h1[k][0];
        #pragma unroll
        for (int i = 0; i < 16; i++) {
            ulonglong2 h2 = hp[i];
            a0 = fma2(w2r[i].x, h2.x, a0);
            a1 = fma2(w2r[i].y, h2.y, a1);
        }
        m = fmaxf(m, lrelu((red2(a0) + red2(a1)) * sc2 + sb2));
    }
    d_feats[q * 192 + c] = m;
}

// ---------------- stage 2: edge(x1) -> conv3 -> conv4 -> max -> x2 ------------
__global__ void __launch_bounds__(64) stage2_kernel(
    const float* __restrict__ W3, const float* __restrict__ s3, const float* __restrict__ b3,
    const float* __restrict__ W4, const float* __restrict__ s4, const float* __restrict__ b4) {
    int q = blockIdx.x; int c = threadIdx.x;
    __shared__ __align__(16) float nbF[KK][64];
    __shared__ __align__(16) float h[KK][64];
    __shared__ int sj[KK];
    if (c < KK) sj[c] = d_idx[q * KK + c];
    __syncthreads();
    int rowbase = q & ~4095;
    #pragma unroll 8
    for (int k = 0; k < KK; k++) nbF[k][c] = d_feats[(rowbase + sj[k]) * 192 + c];
    ulonglong2 w2r[16];
    #pragma unroll
    for (int i = 0; i < 16; i++) w2r[i] = ((const ulonglong2*)(W3 + c * 128))[i];
    float cc = d_cst[q * 64 + c];
    float sc = s3[c], sb = b3[c];
    __syncthreads();
    #pragma unroll 2
    for (int k = 0; k < KK; k++) {
        ull a0 = 0ULL, a1 = 0ULL;
        const ulonglong2* hp = (const ulonglong2*)&nbF[k][0];
        #pragma unroll
        for (int i = 0; i < 16; i++) {
            ulonglong2 h2 = hp[i];
            a0 = fma2(w2r[i].x, h2.x, a0);
            a1 = fma2(w2r[i].y, h2.y, a1);
        }
        h[k][c] = lrelu((cc + red2(a0) + red2(a1)) * sc + sb);
    }
    __syncthreads();
    #pragma unroll
    for (int i = 0; i < 16; i++) w2r[i] = ((const ulonglong2*)(W4 + c * 64))[i];
    float sc4 = s4[c], sb4 = b4[c];
    float m = -3.4e38f;
    #pragma unroll 2
    for (int k = 0; k < KK; k++) {
        ull a0 = 0ULL, a1 = 0ULL;
        const ulonglong2* hp = (const ulonglong2*)&h[k][0];
        #pragma unroll
        for (int i = 0; i < 16; i++) {
            ulonglong2 h2 = hp[i];
            a0 = fma2(w2r[i].x, h2.x, a0);
            a1 = fma2(w2r[i].y, h2.y, a1);
        }
        m = fmaxf(m, lrelu((red2(a0) + red2(a1)) * sc4 + sb4));
    }
    d_feats[q * 192 + 64 + c] = m;
}

// ---------------- stage 3: edge(x2) -> conv5 -> max -> x3 ---------------------
__global__ void __launch_bounds__(64) stage3_kernel(
    const float* __restrict__ W5, const float* __restrict__ s5, const float* __restrict__ b5) {
    int q = blockIdx.x; int c = threadIdx.x;
    __shared__ __align__(16) float nbF[KK][64];
    __shared__ int sj[KK];
    if (c < KK) sj[c] = d_idx[q * KK + c];
    __syncthreads();
    int rowbase = q & ~4095;
    #pragma unroll 8
    for (int k = 0; k < KK; k++) nbF[k][c] = d_feats[(rowbase + sj[k]) * 192 + 64 + c];
    ulonglong2 w2r[16];
    #pragma unroll
    for (int i = 0; i < 16; i++) w2r[i] = ((const ulonglong2*)(W5 + c * 128))[i];
    float cc = d_cst[q * 64 + c];
    float sc = s5[c], sb = b5[c];
    __syncthreads();
    float m = -3.4e38f;
    #pragma unroll 2
    for (int k = 0; k < KK; k++) {
        ull a0 = 0ULL, a1 = 0ULL;
        const ulonglong2* hp = (const ulonglong2*)&nbF[k][0];
        #pragma unroll
        for (int i = 0; i < 16; i++) {
            ulonglong2 h2 = hp[i];
            a0 = fma2(w2r[i].x, h2.x, a0);
            a1 = fma2(w2r[i].y, h2.y, a1);
        }
        m = fmaxf(m, lrelu((cc + red2(a0) + red2(a1)) * sc + sb));
    }
    d_feats[q * 192 + 128 + c] = m;
}

// ---------------- generic tiled GEMM: C[M,N] = A[M,K] @ B[N,K]^T --------------
// f32x2 microkernel: pairs over K. Thread (tx,ty) owns m = mBase+ty+mi*16,
// n = nBase+tx+ni*16 (mi,ni in 0..3). Smem rows padded to 18 floats so the
// 64-bit LDS reads (row*9 mod 16) hit all bank-pairs distinctly; tile fill
// uses float2 stores (8B-aligned for every row since 72 % 8 == 0).
// EPI: 0 plain store, 1 scale/bias/lrelu, 2 +gterm then scale/bias/lrelu,
//      3 conv6 (col-max + atomicMax, no store), 4 conv9 (bias, transposed store)
template <int EPI>
__global__ void __launch_bounds__(256) gemm_k(
    const float* __restrict__ A, int lda,
    const float* __restrict__ B, int ldb, int nrows,
    int K, float* __restrict__ C, int ldc,
    const float* __restrict__ sv, const float* __restrict__ bv) {
    __shared__ __align__(16) float As[64][18];
    __shared__ __align__(16) float Bs[64][18];
    int tid = threadIdx.x;
    int tx = tid & 15, ty = tid >> 4;
    int mBase = blockIdx.y * 64, nBase = blockIdx.x * 64;
    int lr = tid >> 2, lc = (tid & 3) * 4;
    const float* Ap = A + (mBase + lr) * lda + lc;
    const float* Bp = B + (nBase + lr) * ldb + lc;
    bool bval = (nBase + lr) < nrows;
    ull acc2[4][4] = {};
    for (int kt = 0; kt < K; kt += 16) {
        float4 av = *(const float4*)(Ap + kt);
        float4 bw = bval ? *(const float4*)(Bp + kt) : make_float4(0.f, 0.f, 0.f, 0.f);
        __syncthreads();
        *(float2*)&As[lr][lc]     = make_float2(av.x, av.y);
        *(float2*)&As[lr][lc + 2] = make_float2(av.z, av.w);
        *(float2*)&Bs[lr][lc]     = make_float2(bw.x, bw.y);
        *(float2*)&Bs[lr][lc + 2] = make_float2(bw.z, bw.w);
        __syncthreads();
        #pragma unroll
        for (int kk = 0; kk < 8; kk++) {
            ull a2[4], b2[4];
            #pragma unroll
            for (int mi = 0; mi < 4; mi++) a2[mi] = *(const ull*)&As[ty + mi * 16][kk * 2];
            #pragma unroll
            for (int ni = 0; ni < 4; ni++) b2[ni] = *(const ull*)&Bs[tx + ni * 16][kk * 2];
            #pragma unroll
            for (int mi = 0; mi < 4; mi++)
                #pragma unroll
                for (int ni = 0; ni < 4; ni++)
                    acc2[mi][ni] = fma2(a2[mi], b2[ni], acc2[mi][ni]);
        }
    }
    float acc[4][4];
    #pragma unroll
    for (int mi = 0; mi < 4; mi++)
        #pragma unroll
        for (int ni = 0; ni < 4; ni++) acc[mi][ni] = red2(acc2[mi][ni]);

    if (EPI == 3) {
        int bb = mBase >> 12;
        float cm[4];
        #pragma unroll
        for (int ni = 0; ni < 4; ni++) {
            int nn = nBase + tx + ni * 16;
            float s = sv[nn], bbv = bv[nn];
            float m = lrelu(acc[0][ni] * s + bbv);
            m = fmaxf(m, lrelu(acc[1][ni] * s + bbv));
            m = fmaxf(m, lrelu(acc[2][ni] * s + bbv));
            m = fmaxf(m, lrelu(acc[3][ni] * s + bbv));
            cm[ni] = m;
        }
        float* stage = &As[0][0];   // 1152 floats >= 16*64
        __syncthreads();
        #pragma unroll
        for (int ni = 0; ni < 4; ni++) stage[ty * 64 + tx + ni * 16] = cm[ni];
        __syncthreads();
        if (tid < 64) {
            float m = stage[tid];
            #pragma unroll
            for (int r = 1; r < 16; r++) m = fmaxf(m, stage[r * 64 + tid]);
            atomicMax(&d_gmax[bb * 1024 + nBase + tid], fkey(m));
        }
        return;
    }

    #pragma unroll
    for (int mi = 0; mi < 4; mi++) {
        int m = mBase + ty + mi * 16;
        #pragma unroll
        for (int ni = 0; ni < 4; ni++) {
            int n = nBase + tx + ni * 16;
            float a = acc[mi][ni];
            if (EPI == 0) {
                C[m * ldc + n] = a;
            } else if (EPI == 1) {
                C[m * ldc + n] = lrelu(a * sv[n] + bv[n]);
            } else if (EPI == 2) {
                int bb = m >> 12;
                C[m * ldc + n] = lrelu((a + d_gterm[bb * 512 + n]) * sv[n] + bv[n]);
            } else { // EPI == 4 : conv9, transposed output (B,63,N)
                if (n < 63) {
                    int bb = m >> 12; int nn = m & 4095;
                    C[(bb * 63 + n) * 4096 + nn] = a + bv[n];
                }
            }
        }
    }
}

// ---------------- gterm: g[b] @ W7[:, :1024]^T --------------------------------
__global__ void __launch_bounds__(256) gterm_kernel(const float* __restrict__ W7) {
    int b = blockIdx.x >> 3;
    int cg = blockIdx.x & 7;   // group of 64 couts
    __shared__ float gs[1024];
    __shared__ float warpsum[8];
    int tid = threadIdx.x;
    for (int i = tid; i < 1024; i += 256) gs[i] = fdecode(d_gmax[b * 1024 + i]);
    __syncthreads();
    for (int cl = 0; cl < 64; cl++) {
        int cOut = cg * 64 + cl;
        float4 wv = ((const float4*)(W7 + cOut * 1216))[tid];
        float4 g4 = *(const float4*)&gs[tid * 4];
        float p = wv.x * g4.x + wv.y * g4.y + wv.z * g4.z + wv.w * g4.w;
        #pragma unroll
        for (int o = 16; o > 0; o >>= 1) p += __shfl_down_sync(0xffffffffu, p, o);
        if ((tid & 31) == 0) warpsum[tid >> 5] = p;
        __syncthreads();
        if (tid == 0) {
            float s = 0;
            #pragma unroll
            for (int r = 0; r < 8; r++) s += warpsum[r];
            d_gterm[b * 512 + cOut] = s;
        }
        __syncthreads();
    }
}

// ---------------- host --------------------------------------------------------
extern "C" void kernel_launch(void* const* d_in, const int* in_sizes, int n_in,
                              void* d_out, int out_size) {
    const float* x  = (const float*)d_in[0];
    const float* W1 = (const float*)d_in[1];
    const float* s1 = (const float*)d_in[2];
    const float* b1 = (const float*)d_in[3];
    const float* W2 = (const float*)d_in[4];
    const float* s2 = (const float*)d_in[5];
    const float* b2 = (const float*)d_in[6];
    const float* W3 = (const float*)d_in[7];
    const float* s3 = (const float*)d_in[8];
    const float* b3 = (const float*)d_in[9];
    const float* W4 = (const float*)d_in[10];
    const float* s4 = (const float*)d_in[11];
    const float* b4 = (const float*)d_in[12];
    const float* W5 = (const float*)d_in[13];
    const float* s5 = (const float*)d_in[14];
    const float* b5 = (const float*)d_in[15];
    const float* W6 = (const float*)d_in[16];
    const float* s6 = (const float*)d_in[17];
    const float* b6 = (const float*)d_in[18];
    const float* W7 = (const float*)d_in[19];
    const float* s7 = (const float*)d_in[20];
    const float* b7 = (const float*)d_in[21];
    const float* W8 = (const float*)d_in[22];
    const float* s8 = (const float*)d_in[23];
    const float* b8 = (const float*)d_in[24];
    const float* W9 = (const float*)d_in[25];
    const float* b9 = (const float*)d_in[26];
    float* out = (float*)d_out;

    float *feats, *cst, *h7, *h8, *wd3, *wd5;
    cudaGetSymbolAddress((void**)&feats, d_feats);
    cudaGetSymbolAddress((void**)&cst,   d_cst);
    cudaGetSymbolAddress((void**)&h7,    d_h7);
    cudaGetSymbolAddress((void**)&h8,    d_h8);
    cudaGetSymbolAddress((void**)&wd3,   d_wd3);
    cudaGetSymbolAddress((void**)&wd5,   d_wd5);

    prep_kernel<<<48, 256>>>(W3, W5);
    knn_kernel<<<BN_TOT, 128>>>(x);
    stage1_kernel<<<BN_TOT, 64>>>(x, W1, s1, b1, W2, s2, b2);
    // cst for stage2: x1 @ (W3hi - W3lo)^T
    gemm_k<0><<<dim3(1, 256), 256>>>(feats, 192, wd3, 64, 64, 64, cst, 64, nullptr, nullptr);
    stage2_kernel<<<BN_TOT, 64>>>(W3, s3, b3, W4, s4, b4);
    // cst for stage3: x2 @ (W5hi - W5lo)^T
    gemm_k<0><<<dim3(1, 256), 256>>>(feats + 64, 192, wd5, 64, 64, 64, cst, 64, nullptr, nullptr);
    stage3_kernel<<<BN_TOT, 64>>>(W5, s5, b5);
    // conv6 + global max over N (per batch, per channel)
    gemm_k<3><<<dim3(16, 256), 256>>>(feats, 192, W6, 192, 1024, 192, nullptr, 0, s6, b6);
    // gterm[b] = g[b] @ W7[:, :1024]^T
    gterm_kernel<<<32, 256>>>(W7);
    // conv7 on feature part only (K=192) + gterm in epilogue
    gemm_k<2><<<dim3(8, 256), 256>>>(feats, 192, W7 + 1024, 1216, 512, 192, h7, 512, s7, b7);
    // conv8
    gemm_k<1><<<dim3(4, 256), 256>>>(h7, 512, W8, 512, 256, 512, h8, 256, s8, b8);
    // conv9 -> transposed output (B, 63, N)
    gemm_k<4><<<dim3(1, 256), 256>>>(h8, 256, W9, 256, 63, 256, out, 0, nullptr, b9);
}